// round 7
// baseline (speedup 1.0000x reference)
#include <cuda_runtime.h>

// RelLearnableMultiHeadAttn: out[i,j,b,n] = AC + BD
//   AC[i,j,b,n] = sum_d (q[i,b,n,d] + rwb[n,d]) * k[j,b,n,d]
//   BD[i,j,b,n] (rel_shift of B_+D_), with t = j - i:
//     t <= 0 : dot(q[i],   re[K-1+t]) + rbias[K-1+t]
//     t == 1 : 0
//     t >= 2 : dot(q[i+1], re[t-2])   + rbias[t-2]
// Fused: per output tile, stage re rows indexed by u = t - t_lo.

#define QL 1024
#define KL 1024
#define NH 16
#define BN 64          // B * NH
#define DH 64
#define TI 64
#define TJ 64
#define TW 127         // TI + TJ - 1
#define ROWF 68        // padded smem row (floats), keeps float4 alignment

// scratch in (bn, i, j) layout for coalesced GEMM writes; transposed after.
__device__ float g_scratch[(size_t)BN * QL * KL];

template <int MODE>
__device__ __forceinline__ void compute_tile(
    const float* __restrict__ q_s, const float* __restrict__ k_s,
    const float* __restrict__ re_s, float acc[4][4],
    int il0, int jl0, int thr)
{
    const int ubase = jl0 - il0 + (TI - 1);      // in [3, 123]
    const float4* q4 = (const float4*)q_s;
    const float4* k4 = (const float4*)k_s;
    const float4* r4 = (const float4*)re_s;
    #pragma unroll 4
    for (int d4 = 0; d4 < DH / 4; d4++) {
        float4 qa[5], kv[4], rv[7];
        #pragma unroll
        for (int r = 0; r < 5; r++) qa[r] = q4[(il0 + r) * (ROWF / 4) + d4];
        #pragma unroll
        for (int c = 0; c < 4; c++) kv[c] = k4[(jl0 + c) * (ROWF / 4) + d4];
        #pragma unroll
        for (int x = 0; x < 7; x++) rv[x] = r4[(ubase - 3 + x) * (ROWF / 4) + d4];
        #pragma unroll
        for (int r = 0; r < 4; r++) {
            #pragma unroll
            for (int c = 0; c < 4; c++) {
                float4 a1 = qa[r];
                float4 a2;
                if (MODE == 0)      a2 = qa[r];         // all t <= 0
                else if (MODE == 1) a2 = qa[r + 1];     // all t >= 1
                else                a2 = ((c - r) >= thr) ? qa[r + 1] : qa[r];
                float4 b = kv[c];
                float4 e = rv[c - r + 3];
                float s = acc[r][c];
                s += a1.x * b.x; s += a1.y * b.y; s += a1.z * b.z; s += a1.w * b.w;
                s += a2.x * e.x; s += a2.y * e.y; s += a2.z * e.z; s += a2.w * e.w;
                acc[r][c] = s;
            }
        }
    }
}

__global__ void __launch_bounds__(256, 2)
attn_kernel(const float* __restrict__ q, const float* __restrict__ k,
            const float* __restrict__ re, const float* __restrict__ rwb,
            const float* __restrict__ rb)
{
    extern __shared__ float smem[];
    float* q_s  = smem;                        // (TI+1) * ROWF
    float* k_s  = q_s + (TI + 1) * ROWF;       // TJ * ROWF
    float* re_s = k_s + TJ * ROWF;             // TW * ROWF
    __shared__ float rb_s[TW];
    __shared__ float kb_s[TJ];
    __shared__ float rwb_s[DH];

    const int tid = threadIdx.x;
    const int bn  = blockIdx.z;
    const int n   = bn & (NH - 1);
    const int i0  = blockIdx.y * TI;
    const int j0  = blockIdx.x * TJ;
    const int t_lo = j0 - i0 - (TI - 1);

    // ---- load q rows i0..i0+TI (clamped top row; its data is never used
    //      with nonzero re when invalid) ----
    const float4* qg = (const float4*)q;
    for (int idx = tid; idx < (TI + 1) * 16; idx += 256) {
        int row = idx >> 4, c4 = idx & 15;
        int gi = i0 + row; if (gi > QL - 1) gi = QL - 1;
        float4 v = qg[(gi * BN + bn) * 16 + c4];
        ((float4*)(q_s + row * ROWF))[c4] = v;
    }
    // ---- load k rows j0..j0+TJ-1 ----
    const float4* kg = (const float4*)k;
    for (int idx = tid; idx < TJ * 16; idx += 256) {
        int row = idx >> 4, c4 = idx & 15;
        float4 v = kg[((j0 + row) * BN + bn) * 16 + c4];
        ((float4*)(k_s + row * ROWF))[c4] = v;
    }
    // ---- load re rows indexed by u (t = t_lo + u); t==1 slot is zeros ----
    const float4* rg = (const float4*)re;
    for (int idx = tid; idx < TW * 16; idx += 256) {
        int u = idx >> 4, c4 = idx & 15;
        int t = t_lo + u;
        float4 v = make_float4(0.f, 0.f, 0.f, 0.f);
        if (t != 1) {
            int c = (t <= 0) ? (KL - 1 + t) : (t - 2);
            v = rg[(c * NH + n) * 16 + c4];
        }
        ((float4*)(re_s + u * ROWF))[c4] = v;
    }
    if (tid < TW) {
        int t = t_lo + tid;
        rb_s[tid] = (t == 1) ? 0.f
                  : rb[((t <= 0) ? (KL - 1 + t) : (t - 2)) * NH + n];
    }
    if (tid < DH) rwb_s[tid] = rwb[n * DH + tid];
    __syncthreads();

    // kb[j] = dot(rwb, k[j])  (folds the +rwb of AC into a per-column scalar)
    if (tid < TJ) {
        float s = 0.f;
        #pragma unroll 16
        for (int d = 0; d < DH; d++) s += rwb_s[d] * k_s[tid * ROWF + d];
        kb_s[tid] = s;
    }
    __syncthreads();

    const int ty = tid >> 4, tx = tid & 15;
    const int il0 = ty * 4, jl0 = tx * 4;
    float acc[4][4];
    #pragma unroll
    for (int r = 0; r < 4; r++)
        #pragma unroll
        for (int c = 0; c < 4; c++) acc[r][c] = 0.f;

    const int diff = j0 - i0;
    if (diff <= -TI)     compute_tile<0>(q_s, k_s, re_s, acc, il0, jl0, 0);
    else if (diff >= TI) compute_tile<1>(q_s, k_s, re_s, acc, il0, jl0, 0);
    else                 compute_tile<2>(q_s, k_s, re_s, acc, il0, jl0,
                                         1 - diff + il0 - jl0);

    // ---- epilogue: + kb[j] + rbias[c(t)]; write (bn,i,j) scratch ----
    const int ubase = jl0 - il0 + (TI - 1);
    float* sc = g_scratch + ((size_t)bn * QL + (i0 + il0)) * KL + (j0 + jl0);
    #pragma unroll
    for (int r = 0; r < 4; r++) {
        float4 v;
        v.x = acc[r][0] + kb_s[jl0 + 0] + rb_s[ubase + 0 - r];
        v.y = acc[r][1] + kb_s[jl0 + 1] + rb_s[ubase + 1 - r];
        v.z = acc[r][2] + kb_s[jl0 + 2] + rb_s[ubase + 2 - r];
        v.w = acc[r][3] + kb_s[jl0 + 3] + rb_s[ubase + 3 - r];
        *(float4*)(sc + (size_t)r * KL) = v;
    }
}

// (bn, f) -> (f, bn),  f = i*KL + j.  64 x 64 tiles through smem.
__global__ void __launch_bounds__(256)
transpose_kernel(float* __restrict__ out)
{
    __shared__ float ts[64][65];
    const int tid = threadIdx.x;
    const size_t f0 = (size_t)blockIdx.x * 64;
    const float4* sg = (const float4*)g_scratch;
    #pragma unroll
    for (int it = 0; it < 4; it++) {
        int idx = it * 256 + tid;
        int r = idx >> 4;           // bn
        int c4 = idx & 15;
        float4 v = sg[(size_t)r * (QL * (size_t)KL / 4) + (f0 >> 2) + c4];
        ts[r][c4 * 4 + 0] = v.x; ts[r][c4 * 4 + 1] = v.y;
        ts[r][c4 * 4 + 2] = v.z; ts[r][c4 * 4 + 3] = v.w;
    }
    __syncthreads();
    float4* og = (float4*)out;
    #pragma unroll
    for (int it = 0; it < 4; it++) {
        int idx = it * 256 + tid;
        int f = idx >> 4;           // local flat ij
        int b4 = idx & 15;
        float4 w;
        w.x = ts[b4 * 4 + 0][f]; w.y = ts[b4 * 4 + 1][f];
        w.z = ts[b4 * 4 + 2][f]; w.w = ts[b4 * 4 + 3][f];
        og[(f0 + (size_t)f) * 16 + b4] = w;
    }
}

extern "C" void kernel_launch(void* const* d_in, const int* in_sizes, int n_in,
                              void* d_out, int out_size)
{
    (void)in_sizes; (void)n_in; (void)out_size;
    const float* q   = (const float*)d_in[0];
    const float* k   = (const float*)d_in[1];
    const float* re  = (const float*)d_in[2];
    const float* rwb = (const float*)d_in[3];
    const float* rb  = (const float*)d_in[4];

    const int smem_bytes = ((TI + 1) + TJ + TW) * ROWF * (int)sizeof(float); // 69632
    cudaFuncSetAttribute(attn_kernel,
                         cudaFuncAttributeMaxDynamicSharedMemorySize, smem_bytes);

    dim3 g1(KL / TJ, QL / TI, BN);
    attn_kernel<<<g1, 256, smem_bytes>>>(q, k, re, rwb, rb);
    transpose_kernel<<<(QL * KL) / 64, 256>>>((float*)d_out);
}

// round 9
// speedup vs baseline: 3.9730x; 3.9730x over previous
#include <cuda_runtime.h>

// RelLearnableMultiHeadAttn, two-pass tensor-core version.
// Pass 1 (gemm_kernel, tf32 mma.sync): for each beta in [0,128):
//   beta <  64: S[bn]  = (Q_bn + rwb_n) . K_bn^T      -> g_scr[beta]
//   beta >= 64: B_[bn] = Q_bn . RE_n^T                -> g_scr[beta]
// Pass 2 (combine_kernel): out[(i*1024+j)*64 + bn] =
//   S[bn,i,j] + BD + 0/rbias, where with t = j-i:
//     t<=0: B_[bn, i,   1023+t] + rb[1023+t, n]
//     t==1: 0
//     t>=2: B_[bn, i+1, t-2]    + rb[t-2,  n]
// (t>=2 implies i <= 1021, so row i+1 is always in range.)

#define QL 1024
#define KL 1024
#define NH 16
#define BN 64
#define DH 64

// [beta][i][j], beta in [0,128): 512 MB scratch.
__device__ float g_scr[(size_t)128 * QL * KL];

__device__ __forceinline__ unsigned f2tf(float x) {
    unsigned r;
    asm("cvt.rna.tf32.f32 %0, %1;" : "=r"(r) : "f"(x));
    return r;
}

__device__ __forceinline__ void mma_tf32(float* d, const unsigned* a, const unsigned* b) {
    asm volatile(
        "mma.sync.aligned.m16n8k8.row.col.f32.tf32.tf32.f32 "
        "{%0,%1,%2,%3}, {%4,%5,%6,%7}, {%8,%9}, {%0,%1,%2,%3};"
        : "+f"(d[0]), "+f"(d[1]), "+f"(d[2]), "+f"(d[3])
        : "r"(a[0]), "r"(a[1]), "r"(a[2]), "r"(a[3]), "r"(b[0]), "r"(b[1]));
}

// 128x128 tile per CTA, K=64. 256 threads = 8 warps in a 4(i) x 2(j) grid;
// each warp: 32x64 via 2(m) x 8(n) m16n8k8 fragments, 8 k-steps.
__global__ void __launch_bounds__(256, 2)
gemm_kernel(const float* __restrict__ q, const float* __restrict__ k,
            const float* __restrict__ re, const float* __restrict__ rwb)
{
    extern __shared__ unsigned sm[];
    unsigned* a_s = sm;              // 128 rows x 68 (64 data + 4 pad)
    unsigned* b_s = sm + 128 * 68;

    const int tid  = threadIdx.x;
    const int beta = blockIdx.z;
    const int bn   = beta & 63;
    const int n    = bn & (NH - 1);
    const bool isAC = beta < 64;
    const int i0 = blockIdx.y * 128;
    const int j0 = blockIdx.x * 128;

    const int c4 = tid & 15;   // float4 column, fixed per thread
    const int r0 = tid >> 4;   // base row within 16-row stripe

    // ---- stage A = Q rows i0..i0+127 (+rwb if AC), cvt to tf32 ----
    float4 wb = make_float4(0.f, 0.f, 0.f, 0.f);
    if (isAC) wb = ((const float4*)(rwb + n * DH))[c4];
    #pragma unroll
    for (int it = 0; it < 8; it++) {
        int r = it * 16 + r0;
        float4 v = ((const float4*)q)[((size_t)(i0 + r) * BN + bn) * 16 + c4];
        unsigned* d = a_s + r * 68 + c4 * 4;
        d[0] = f2tf(v.x + wb.x); d[1] = f2tf(v.y + wb.y);
        d[2] = f2tf(v.z + wb.z); d[3] = f2tf(v.w + wb.w);
    }
    // ---- stage B = K rows (AC) or RE rows (B_) j0..j0+127 ----
    #pragma unroll
    for (int it = 0; it < 8; it++) {
        int r = it * 16 + r0;
        float4 v;
        if (isAC) v = ((const float4*)k)[((size_t)(j0 + r) * BN + bn) * 16 + c4];
        else      v = ((const float4*)re)[((size_t)(j0 + r) * NH + n) * 16 + c4];
        unsigned* d = b_s + r * 68 + c4 * 4;
        d[0] = f2tf(v.x); d[1] = f2tf(v.y); d[2] = f2tf(v.z); d[3] = f2tf(v.w);
    }
    __syncthreads();

    const int lane = tid & 31, w = tid >> 5;
    const int wi = (w & 3) * 32;   // warp row base
    const int wj = (w >> 2) * 64;  // warp col base
    const int gr = lane >> 2, tg = lane & 3;

    float acc[2][8][4];
    #pragma unroll
    for (int m = 0; m < 2; m++)
        #pragma unroll
        for (int nf = 0; nf < 8; nf++)
            #pragma unroll
            for (int e = 0; e < 4; e++) acc[m][nf][e] = 0.f;

    #pragma unroll
    for (int k0 = 0; k0 < DH; k0 += 8) {
        unsigned af[2][4], bf[8][2];
        #pragma unroll
        for (int m = 0; m < 2; m++) {
            int r = wi + m * 16 + gr;
            af[m][0] = a_s[r * 68 + k0 + tg];
            af[m][1] = a_s[(r + 8) * 68 + k0 + tg];
            af[m][2] = a_s[r * 68 + k0 + tg + 4];
            af[m][3] = a_s[(r + 8) * 68 + k0 + tg + 4];
        }
        #pragma unroll
        for (int nf = 0; nf < 8; nf++) {
            int c = wj + nf * 8 + gr;
            bf[nf][0] = b_s[c * 68 + k0 + tg];
            bf[nf][1] = b_s[c * 68 + k0 + tg + 4];
        }
        #pragma unroll
        for (int m = 0; m < 2; m++)
            #pragma unroll
            for (int nf = 0; nf < 8; nf++)
                mma_tf32(acc[m][nf], af[m], bf[nf]);
    }

    // ---- epilogue: float2 stores, 32B-sector-exact ----
    float* sc = g_scr + (size_t)beta * (QL * (size_t)KL);
    #pragma unroll
    for (int m = 0; m < 2; m++) {
        int rA = i0 + wi + m * 16 + gr;
        #pragma unroll
        for (int nf = 0; nf < 8; nf++) {
            int c = j0 + wj + nf * 8 + tg * 2;
            *(float2*)(sc + (size_t)rA * KL + c) =
                make_float2(acc[m][nf][0], acc[m][nf][1]);
            *(float2*)(sc + (size_t)(rA + 8) * KL + c) =
                make_float2(acc[m][nf][2], acc[m][nf][3]);
        }
    }
}

// Combine + shift + bias + transpose to (f, bn), f = i*1024 + j.
__global__ void __launch_bounds__(256)
combine_kernel(const float* __restrict__ rb, float* __restrict__ out)
{
    __shared__ float ts[64][65];
    const int tid = threadIdx.x;
    const size_t f0 = (size_t)blockIdx.x * 64;
    const int i  = (int)(f0 >> 10);
    const int j0 = (int)(f0 & 1023);
    const int c4 = tid & 15;
    const int rbase = tid >> 4;

    #pragma unroll
    for (int it = 0; it < 4; it++) {
        int bn = it * 16 + rbase;
        int n  = bn & (NH - 1);
        float4 s4 = *(const float4*)(g_scr + (size_t)bn * (QL * (size_t)KL)
                                     + ((size_t)i << 10) + j0 + c4 * 4);
        const float* Bp = g_scr + (size_t)(64 + bn) * (QL * (size_t)KL);
        float v[4] = {s4.x, s4.y, s4.z, s4.w};
        #pragma unroll
        for (int e = 0; e < 4; e++) {
            int j = j0 + c4 * 4 + e;
            int t = j - i;
            if (t != 1) {
                int ri = (t <= 0) ? i : (i + 1);
                int c  = (t <= 0) ? (1023 + t) : (t - 2);
                v[e] += Bp[((size_t)ri << 10) + c] + rb[c * NH + n];
            }
        }
        ts[bn][c4 * 4 + 0] = v[0]; ts[bn][c4 * 4 + 1] = v[1];
        ts[bn][c4 * 4 + 2] = v[2]; ts[bn][c4 * 4 + 3] = v[3];
    }
    __syncthreads();

    float4* og = (float4*)out;
    #pragma unroll
    for (int it = 0; it < 4; it++) {
        int idx = it * 256 + tid;
        int f  = idx >> 4;   // local flat ij
        int b4 = idx & 15;
        float4 wv;
        wv.x = ts[b4 * 4 + 0][f]; wv.y = ts[b4 * 4 + 1][f];
        wv.z = ts[b4 * 4 + 2][f]; wv.w = ts[b4 * 4 + 3][f];
        og[(f0 + (size_t)f) * 16 + b4] = wv;
    }
}

extern "C" void kernel_launch(void* const* d_in, const int* in_sizes, int n_in,
                              void* d_out, int out_size)
{
    (void)in_sizes; (void)n_in; (void)out_size;
    const float* q   = (const float*)d_in[0];
    const float* k   = (const float*)d_in[1];
    const float* re  = (const float*)d_in[2];
    const float* rwb = (const float*)d_in[3];
    const float* rb  = (const float*)d_in[4];

    const int smem_bytes = 2 * 128 * 68 * (int)sizeof(unsigned); // 69632
    cudaFuncSetAttribute(gemm_kernel,
                         cudaFuncAttributeMaxDynamicSharedMemorySize, smem_bytes);

    dim3 gA(KL / 128, QL / 128, 128);
    gemm_kernel<<<gA, 256, smem_bytes>>>(q, k, re, rwb);
    combine_kernel<<<(QL * KL) / 64, 256>>>(rb, (float*)d_out);
}

// round 11
// speedup vs baseline: 4.8093x; 1.2105x over previous
#include <cuda_runtime.h>

// RelLearnableMultiHeadAttn, two-pass tensor-core version.
// Pass 1 (gemm_kernel, tf32 mma.sync): for each beta in [0,128):
//   beta <  64: S[bn]  = (Q_bn + rwb_n) . K_bn^T                 -> g_scr[beta]
//   beta >= 64: B'[bn] = Q_bn . RE_n^T + rb[c,n] (rb folded in)  -> g_scr[beta]
// Pass 2 (combine_kernel): out[(i*1024+j)*64 + bn] =
//   S[bn,i,j] + BD, where with t = j-i:
//     t<=0: B'[bn, i,   1023+t]
//     t==1: 0
//     t>=2: B'[bn, i+1, t-2]
// (t>=2 implies i <= 1021, so row i+1 is always in range.)

#define QL 1024
#define KL 1024
#define NH 16
#define BN 64
#define DH 64

// [beta][i][j], beta in [0,128): 512 MB scratch.
__device__ float g_scr[(size_t)128 * QL * KL];

__device__ __forceinline__ unsigned f2tf(float x) {
    unsigned r;
    asm("cvt.rna.tf32.f32 %0, %1;" : "=r"(r) : "f"(x));
    return r;
}

__device__ __forceinline__ void mma_tf32(float* d, const unsigned* a, const unsigned* b) {
    asm volatile(
        "mma.sync.aligned.m16n8k8.row.col.f32.tf32.tf32.f32 "
        "{%0,%1,%2,%3}, {%4,%5,%6,%7}, {%8,%9}, {%0,%1,%2,%3};"
        : "+f"(d[0]), "+f"(d[1]), "+f"(d[2]), "+f"(d[3])
        : "r"(a[0]), "r"(a[1]), "r"(a[2]), "r"(a[3]), "r"(b[0]), "r"(b[1]));
}

// 128x128 tile per CTA, K=64. 256 threads = 8 warps in a 4(i) x 2(j) grid;
// each warp: 32x64 via 2(m) x 8(n) m16n8k8 fragments, 8 k-steps.
__global__ void __launch_bounds__(256, 2)
gemm_kernel(const float* __restrict__ q, const float* __restrict__ k,
            const float* __restrict__ re, const float* __restrict__ rwb,
            const float* __restrict__ rb)
{
    extern __shared__ unsigned sm[];
    unsigned* a_s = sm;              // 128 rows x 68 (64 data + 4 pad)
    unsigned* b_s = sm + 128 * 68;
    __shared__ float rb_sl[128];     // rb slice for this CTA's 128 columns

    const int tid  = threadIdx.x;
    const int beta = blockIdx.z;
    const int bn   = beta & 63;
    const int n    = bn & (NH - 1);
    const bool isAC = beta < 64;
    const int i0 = blockIdx.y * 128;
    const int j0 = blockIdx.x * 128;

    const int c4 = tid & 15;   // float4 column, fixed per thread
    const int r0 = tid >> 4;   // base row within 16-row stripe

    // ---- stage A = Q rows i0..i0+127 (+rwb if AC), cvt to tf32 ----
    float4 wb = make_float4(0.f, 0.f, 0.f, 0.f);
    if (isAC) wb = ((const float4*)(rwb + n * DH))[c4];
    #pragma unroll
    for (int it = 0; it < 8; it++) {
        int r = it * 16 + r0;
        float4 v = ((const float4*)q)[((size_t)(i0 + r) * BN + bn) * 16 + c4];
        unsigned* d = a_s + r * 68 + c4 * 4;
        d[0] = f2tf(v.x + wb.x); d[1] = f2tf(v.y + wb.y);
        d[2] = f2tf(v.z + wb.z); d[3] = f2tf(v.w + wb.w);
    }
    // ---- stage B = K rows (AC) or RE rows (B') j0..j0+127 ----
    #pragma unroll
    for (int it = 0; it < 8; it++) {
        int r = it * 16 + r0;
        float4 v;
        if (isAC) v = ((const float4*)k)[((size_t)(j0 + r) * BN + bn) * 16 + c4];
        else      v = ((const float4*)re)[((size_t)(j0 + r) * NH + n) * 16 + c4];
        unsigned* d = b_s + r * 68 + c4 * 4;
        d[0] = f2tf(v.x); d[1] = f2tf(v.y); d[2] = f2tf(v.z); d[3] = f2tf(v.w);
    }
    // ---- stage rb slice (only used for B' blocks) ----
    if (tid < 128) rb_sl[tid] = isAC ? 0.f : rb[(j0 + tid) * NH + n];
    __syncthreads();

    const int lane = tid & 31, w = tid >> 5;
    const int wi = (w & 3) * 32;   // warp row base
    const int wj = (w >> 2) * 64;  // warp col base
    const int gr = lane >> 2, tg = lane & 3;

    float acc[2][8][4];
    #pragma unroll
    for (int m = 0; m < 2; m++)
        #pragma unroll
        for (int nf = 0; nf < 8; nf++)
            #pragma unroll
            for (int e = 0; e < 4; e++) acc[m][nf][e] = 0.f;

    #pragma unroll
    for (int k0 = 0; k0 < DH; k0 += 8) {
        unsigned af[2][4], bf[8][2];
        #pragma unroll
        for (int m = 0; m < 2; m++) {
            int r = wi + m * 16 + gr;
            af[m][0] = a_s[r * 68 + k0 + tg];
            af[m][1] = a_s[(r + 8) * 68 + k0 + tg];
            af[m][2] = a_s[r * 68 + k0 + tg + 4];
            af[m][3] = a_s[(r + 8) * 68 + k0 + tg + 4];
        }
        #pragma unroll
        for (int nf = 0; nf < 8; nf++) {
            int c = wj + nf * 8 + gr;
            bf[nf][0] = b_s[c * 68 + k0 + tg];
            bf[nf][1] = b_s[c * 68 + k0 + tg + 4];
        }
        #pragma unroll
        for (int m = 0; m < 2; m++)
            #pragma unroll
            for (int nf = 0; nf < 8; nf++)
                mma_tf32(acc[m][nf], af[m], bf[nf]);
    }

    // ---- epilogue: +rb (B' blocks), float2 stores, 32B-sector-exact ----
    float* sc = g_scr + (size_t)beta * (QL * (size_t)KL);
    #pragma unroll
    for (int m = 0; m < 2; m++) {
        int rA = i0 + wi + m * 16 + gr;
        #pragma unroll
        for (int nf = 0; nf < 8; nf++) {
            int cl = wj + nf * 8 + tg * 2;     // local column
            float r0b = rb_sl[cl], r1b = rb_sl[cl + 1];
            int c = j0 + cl;
            *(float2*)(sc + (size_t)rA * KL + c) =
                make_float2(acc[m][nf][0] + r0b, acc[m][nf][1] + r1b);
            *(float2*)(sc + (size_t)(rA + 8) * KL + c) =
                make_float2(acc[m][nf][2] + r0b, acc[m][nf][3] + r1b);
        }
    }
}

// Combine + shift + transpose to (f, bn), f = i*1024 + j.
__global__ void __launch_bounds__(256)
combine_kernel(float* __restrict__ out)
{
    __shared__ float ts[64][65];
    const int tid = threadIdx.x;
    const size_t f0 = (size_t)blockIdx.x * 64;
    const int i  = (int)(f0 >> 10);
    const int j0 = (int)(f0 & 1023);
    const int c4 = tid & 15;
    const int rbase = tid >> 4;

    #pragma unroll
    for (int it = 0; it < 4; it++) {
        int bn = it * 16 + rbase;
        float4 s4 = *(const float4*)(g_scr + (size_t)bn * (QL * (size_t)KL)
                                     + ((size_t)i << 10) + j0 + c4 * 4);
        const float* Bp = g_scr + (size_t)(64 + bn) * (QL * (size_t)KL);
        float v[4] = {s4.x, s4.y, s4.z, s4.w};
        #pragma unroll
        for (int e = 0; e < 4; e++) {
            int j = j0 + c4 * 4 + e;
            int t = j - i;
            if (t != 1) {
                int ri = (t <= 0) ? i : (i + 1);
                int c  = (t <= 0) ? (1023 + t) : (t - 2);
                v[e] += Bp[((size_t)ri << 10) + c];
            }
        }
        ts[bn][c4 * 4 + 0] = v[0]; ts[bn][c4 * 4 + 1] = v[1];
        ts[bn][c4 * 4 + 2] = v[2]; ts[bn][c4 * 4 + 3] = v[3];
    }
    __syncthreads();

    float4* og = (float4*)out;
    #pragma unroll
    for (int it = 0; it < 4; it++) {
        int idx = it * 256 + tid;
        int f  = idx >> 4;   // local flat ij
        int b4 = idx & 15;
        float4 wv;
        wv.x = ts[b4 * 4 + 0][f]; wv.y = ts[b4 * 4 + 1][f];
        wv.z = ts[b4 * 4 + 2][f]; wv.w = ts[b4 * 4 + 3][f];
        og[(f0 + (size_t)f) * 16 + b4] = wv;
    }
}

extern "C" void kernel_launch(void* const* d_in, const int* in_sizes, int n_in,
                              void* d_out, int out_size)
{
    (void)in_sizes; (void)n_in; (void)out_size;
    const float* q   = (const float*)d_in[0];
    const float* k   = (const float*)d_in[1];
    const float* re  = (const float*)d_in[2];
    const float* rwb = (const float*)d_in[3];
    const float* rb  = (const float*)d_in[4];

    const int smem_bytes = 2 * 128 * 68 * (int)sizeof(unsigned); // 69632
    cudaFuncSetAttribute(gemm_kernel,
                         cudaFuncAttributeMaxDynamicSharedMemorySize, smem_bytes);

    dim3 gA(KL / 128, QL / 128, 128);
    gemm_kernel<<<gA, 256, smem_bytes>>>(q, k, re, rwb, rb);
    combine_kernel<<<(QL * KL) / 64, 256>>>((float*)d_out);
}